// round 9
// baseline (speedup 1.0000x reference)
#include <cuda_runtime.h>
#include <cuda_bf16.h>
#include <cstdint>
#include <math.h>

#define BB 4
#define NN 4096
#define DD 256
#define KTOP 64
#define EPSN 1e-12f

#define PACKW 512             // [hi(256) | lo(256)] per row
#define NCHUNK_V 12           // value: full 3-term split
#define NCHUNK_C 8            // cos: H·(H+L)^T

// ---------------- scratch ----------------
__device__ float          g_value[(size_t)BB * NN * DD];
__device__ float          g_cos  [(size_t)BB * NN * NN];
__device__ __nv_bfloat16  g_pack [(size_t)BB * NN * PACKW];
__device__ __nv_bfloat16  g_Wpack[(size_t)DD * PACKW];
__device__ float          g_norm [(size_t)BB * NN];
__device__ float          g_xsum_part[BB * 16 * DD];
__device__ float          g_sumv[BB * DD];

__device__ __constant__ int CAMAP_V[NCHUNK_V] = {0,1,2,3, 0,1,2,3, 4,5,6,7};
__device__ __constant__ int CBMAP_V[NCHUNK_V] = {0,1,2,3, 4,5,6,7, 0,1,2,3};

__device__ __forceinline__ uint32_t smem_to_u32(const void* p) {
    uint32_t a;
    asm("{ .reg .u64 t; cvta.to.shared.u64 t, %1; cvt.u32.u64 %0, t; }" : "=r"(a) : "l"(p));
    return a;
}
__device__ __forceinline__ void ldsm4(uint32_t& r0, uint32_t& r1, uint32_t& r2, uint32_t& r3, uint32_t addr) {
    asm volatile("ldmatrix.sync.aligned.m8n8.x4.shared.b16 {%0,%1,%2,%3}, [%4];"
        : "=r"(r0), "=r"(r1), "=r"(r2), "=r"(r3) : "r"(addr));
}
__device__ __forceinline__ void mma16816(float* d, const uint32_t* a, const uint32_t* b) {
    asm volatile("mma.sync.aligned.m16n8k16.row.col.f32.bf16.bf16.f32 "
        "{%0,%1,%2,%3}, {%4,%5,%6,%7}, {%8,%9}, {%0,%1,%2,%3};"
        : "+f"(d[0]), "+f"(d[1]), "+f"(d[2]), "+f"(d[3])
        : "r"(a[0]), "r"(a[1]), "r"(a[2]), "r"(a[3]), "r"(b[0]), "r"(b[1]));
}
__device__ __forceinline__ void cp_async16(uint32_t saddr, const void* gptr) {
    asm volatile("cp.async.cg.shared.global [%0], [%1], 16;" :: "r"(saddr), "l"(gptr) : "memory");
}
#define CP_COMMIT() asm volatile("cp.async.commit_group;" ::: "memory")
#define CP_WAIT(N)  asm volatile("cp.async.wait_group %0;" :: "n"(N) : "memory")

// ---------------- 1) normalize + hi/lo pack + norm save (+ W pack in blocks 0..255) ----------------
__global__ void __launch_bounds__(DD) normalize_pack_kernel(const float* __restrict__ x,
                                                            const float* __restrict__ W)
{
    int row = blockIdx.x;
    int d   = threadIdx.x;
    float v = x[(size_t)row * DD + d];
    float s = v * v;
    __shared__ float red[8];
    #pragma unroll
    for (int o = 16; o; o >>= 1) s += __shfl_xor_sync(0xffffffffu, s, o);
    if ((d & 31) == 0) red[d >> 5] = s;
    __syncthreads();
    if (d < 32) {
        float t = (d < 8) ? red[d] : 0.f;
        #pragma unroll
        for (int o = 4; o; o >>= 1) t += __shfl_xor_sync(0xffffffffu, t, o);
        if (d == 0) red[0] = t;
    }
    __syncthreads();
    float norm = sqrtf(red[0]);
    float nv = v / fmaxf(norm, EPSN);

    __nv_bfloat16 hi = __float2bfloat16(nv);
    __nv_bfloat16 lo = __float2bfloat16(nv - __bfloat162float(hi));

    size_t base = (size_t)row * PACKW;
    g_pack[base + d]       = hi;
    g_pack[base + 256 + d] = lo;
    if (d == 0) g_norm[row] = norm;

    if (row < DD) {   // W pack piggy-back
        float w = W[(size_t)row * DD + d];
        __nv_bfloat16 whi = __float2bfloat16(w);
        __nv_bfloat16 wlo = __float2bfloat16(w - __bfloat162float(whi));
        g_Wpack[(size_t)row * PACKW + d]       = whi;
        g_Wpack[(size_t)row * PACKW + 256 + d] = wlo;
    }
}

// ---------------- 1b) per-batch partial column sums of x ----------------
__global__ void __launch_bounds__(DD) xsum_part_kernel(const float* __restrict__ x)
{
    int b = blockIdx.y, c = blockIdx.x, e = threadIdx.x;
    const float* base = x + (size_t)b * NN * DD + (size_t)c * 256 * DD + e;
    float s = 0.f;
    #pragma unroll 8
    for (int n = 0; n < 256; n++) s += base[(size_t)n * DD];
    g_xsum_part[(b * 16 + c) * DD + e] = s;
}

// ---------------- 1c) sumv = (colsum x) @ W^T + N*b  (exact algebra, tiny matvec) ----------------
__global__ void __launch_bounds__(DD) sumv_mv_kernel(const float* __restrict__ W,
                                                     const float* __restrict__ bias)
{
    int b = blockIdx.x, t = threadIdx.x;
    __shared__ float xs[DD];
    float s = 0.f;
    #pragma unroll
    for (int c = 0; c < 16; c++) s += g_xsum_part[(b * 16 + c) * DD + t];
    xs[t] = s;
    __syncthreads();
    float acc = 0.f;
    const float4* Wr = (const float4*)&W[(size_t)t * DD];
    #pragma unroll 8
    for (int d4 = 0; d4 < 64; d4++) {
        float4 w = Wr[d4];
        acc += xs[d4 * 4 + 0] * w.x + xs[d4 * 4 + 1] * w.y
             + xs[d4 * 4 + 2] * w.z + xs[d4 * 4 + 3] * w.w;
    }
    g_sumv[b * DD + t] = acc + (float)NN * bias[t];
}

// ---------------- 2) value = norm * (nx @ W^T) + b  (bf16 mma, 3-stage pipe, 128x128) ----------------
__global__ void __launch_bounds__(256, 2) valuemma_kernel(const float* __restrict__ bias)
{
    extern __shared__ char smem[];
    const uint32_t sb = smem_to_u32(smem);

    const int tid  = threadIdx.x;
    const int wid  = tid >> 5;
    const int lane = tid & 31;
    const int wm   = wid & 3;
    const int wn   = wid >> 2;
    const int m0   = blockIdx.y * 128;
    const int n0   = blockIdx.x * 128;

    const __nv_bfloat16* Agl = g_pack  + (size_t)m0 * PACKW;
    const __nv_bfloat16* Bgl = g_Wpack + (size_t)n0 * PACKW;

    const int lr = tid >> 3;
    const int lj = tid & 7;

    auto load_chunk_async = [&](int c, int s) {
        const char* ga = (const char*)Agl + (size_t)CAMAP_V[c] * 128;
        const char* gb = (const char*)Bgl + (size_t)CBMAP_V[c] * 128;
        uint32_t sa = sb + s * 32768;
        uint32_t sbm = sa + 16384;
        #pragma unroll
        for (int k = 0; k < 4; k++) {
            int r = lr + 32 * k;
            uint32_t off = r * 128 + ((lj ^ (r & 7)) << 4);
            cp_async16(sa + off,  ga + (size_t)r * (PACKW * 2) + lj * 16);
            cp_async16(sbm + off, gb + (size_t)r * (PACKW * 2) + lj * 16);
        }
    };

    float acc[2][8][4];
    #pragma unroll
    for (int ia = 0; ia < 2; ia++)
        #pragma unroll
        for (int j = 0; j < 8; j++)
            #pragma unroll
            for (int q = 0; q < 4; q++) acc[ia][j][q] = 0.f;

    const int arow_lo = (lane & 7) + ((lane >> 3) & 1) * 8;
    const int a_cc_add = (lane >> 4);
    const int brow_lo = (lane & 7) + ((lane >> 4) ? 8 : 0);
    const int b_cc_add = ((lane >> 3) & 1);

    load_chunk_async(0, 0); CP_COMMIT();
    load_chunk_async(1, 1); CP_COMMIT();

    for (int c = 0; c < NCHUNK_V; c++) {
        if (c + 1 < NCHUNK_V) { CP_WAIT(1); } else { CP_WAIT(0); }
        __syncthreads();
        if (c + 2 < NCHUNK_V) { load_chunk_async(c + 2, (c + 2) % 3); CP_COMMIT(); }

        const uint32_t abase = sb + (c % 3) * 32768;
        const uint32_t bbase = abase + 16384;

        #pragma unroll
        for (int ks = 0; ks < 4; ks++) {
            uint32_t af[2][4], bf[8][2];
            #pragma unroll
            for (int ia = 0; ia < 2; ia++) {
                int row = wm * 32 + ia * 16 + arow_lo;
                uint32_t cc = 2 * ks + a_cc_add;
                uint32_t addr = abase + row * 128 + ((cc << 4) ^ ((row & 7) << 4));
                ldsm4(af[ia][0], af[ia][1], af[ia][2], af[ia][3], addr);
            }
            #pragma unroll
            for (int L = 0; L < 4; L++) {
                int row = wn * 64 + L * 16 + brow_lo;
                uint32_t cc = 2 * ks + b_cc_add;
                uint32_t addr = bbase + row * 128 + ((cc << 4) ^ ((row & 7) << 4));
                ldsm4(bf[2 * L][0], bf[2 * L][1], bf[2 * L + 1][0], bf[2 * L + 1][1], addr);
            }
            #pragma unroll
            for (int ia = 0; ia < 2; ia++)
                #pragma unroll
                for (int j = 0; j < 8; j++)
                    mma16816(acc[ia][j], af[ia], bf[j]);
        }
    }

    const int g = lane >> 2, q = lane & 3;
    #pragma unroll
    for (int ia = 0; ia < 2; ia++) {
        int row = m0 + wm * 32 + ia * 16 + g;
        float nr0 = __ldg(&g_norm[row]);
        float nr8 = __ldg(&g_norm[row + 8]);
        #pragma unroll
        for (int j = 0; j < 8; j++) {
            int col = n0 + wn * 64 + j * 8 + q * 2;
            float b0 = __ldg(&bias[col]), b1 = __ldg(&bias[col + 1]);
            float2 v01 = make_float2(acc[ia][j][0] * nr0 + b0, acc[ia][j][1] * nr0 + b1);
            float2 v23 = make_float2(acc[ia][j][2] * nr8 + b0, acc[ia][j][3] * nr8 + b1);
            *(float2*)&g_value[(size_t)row * DD + col]       = v01;
            *(float2*)&g_value[(size_t)(row + 8) * DD + col] = v23;
        }
    }
}

// ---------------- 4) cos = H @ (H+L)^T, CTA tile 256x128, warp tile 64x64 ----------------
// Tiles: by strips of 256 rows (0..15), bx cols of 128 (0..31), include iff bx <= 2*by+1.
// Mirror whole tile iff bx <= 2*by-1 (diagonal 256^2 squares computed directly; exact cover).
__global__ void __launch_bounds__(256, 1) cosmma_kernel(float* __restrict__ C)
{
    extern __shared__ char smem[];
    const uint32_t sb = smem_to_u32(smem);

    const int tid  = threadIdx.x;
    const int wid  = tid >> 5;
    const int lane = tid & 31;
    const int wm   = wid & 3;        // 0..3 -> 64-row slice
    const int wn   = wid >> 2;       // 0..1 -> 64-col slice
    const int b    = blockIdx.z;

    // decode i -> (by, bx) with cum count by*(by+1)
    int i  = blockIdx.x;
    int by = (int)((sqrtf(4.f * (float)i + 1.f) - 1.f) * 0.5f);
    while ((by + 1) * (by + 2) <= i) by++;
    while (by * (by + 1) > i) by--;
    int bx = i - by * (by + 1);
    const int m0 = by * 256;
    const int n0 = bx * 128;
    const bool do_mirror = (bx <= 2 * by - 1);

    const __nv_bfloat16* Agl = g_pack + ((size_t)b * NN + m0) * PACKW;
    const __nv_bfloat16* Bgl = g_pack + ((size_t)b * NN + n0) * PACKW;

    const int lr = tid >> 3;
    const int lj = tid & 7;
    const int STAGE = 49152;         // A 32KB + B 16KB

    auto load_chunk_async = [&](int c, int s) {
        const char* ga = (const char*)Agl + (size_t)(c & 3) * 128;   // hi only
        const char* gb = (const char*)Bgl + (size_t)c * 128;         // hi then lo
        uint32_t sa = sb + s * STAGE;
        uint32_t sbm = sa + 32768;
        #pragma unroll
        for (int k = 0; k < 8; k++) {          // A: 256 rows
            int r = lr + 32 * k;
            uint32_t off = r * 128 + ((lj ^ (r & 7)) << 4);
            cp_async16(sa + off, ga + (size_t)r * (PACKW * 2) + lj * 16);
        }
        #pragma unroll
        for (int k = 0; k < 4; k++) {          // B: 128 rows
            int r = lr + 32 * k;
            uint32_t off = r * 128 + ((lj ^ (r & 7)) << 4);
            cp_async16(sbm + off, gb + (size_t)r * (PACKW * 2) + lj * 16);
        }
    };

    float acc[4][8][4];
    #pragma unroll
    for (int ia = 0; ia < 4; ia++)
        #pragma unroll
        for (int j = 0; j < 8; j++)
            #pragma unroll
            for (int q = 0; q < 4; q++) acc[ia][j][q] = 0.f;

    const int arow_lo = (lane & 7) + ((lane >> 3) & 1) * 8;
    const int a_cc_add = (lane >> 4);
    const int brow_lo = (lane & 7) + ((lane >> 4) ? 8 : 0);
    const int b_cc_add = ((lane >> 3) & 1);

    load_chunk_async(0, 0); CP_COMMIT();
    load_chunk_async(1, 1); CP_COMMIT();

    for (int c = 0; c < NCHUNK_C; c++) {
        if (c + 1 < NCHUNK_C) { CP_WAIT(1); } else { CP_WAIT(0); }
        __syncthreads();
        if (c + 2 < NCHUNK_C) { load_chunk_async(c + 2, (c + 2) % 3); CP_COMMIT(); }

        const uint32_t abase = sb + (c % 3) * STAGE;
        const uint32_t bbase = abase + 32768;

        #pragma unroll
        for (int ks = 0; ks < 4; ks++) {
            uint32_t af[4][4], bf[8][2];
            #pragma unroll
            for (int ia = 0; ia < 4; ia++) {
                int row = wm * 64 + ia * 16 + arow_lo;
                uint32_t cc = 2 * ks + a_cc_add;
                uint32_t addr = abase + row * 128 + ((cc << 4) ^ ((row & 7) << 4));
                ldsm4(af[ia][0], af[ia][1], af[ia][2], af[ia][3], addr);
            }
            #pragma unroll
            for (int L = 0; L < 4; L++) {
                int row = wn * 64 + L * 16 + brow_lo;
                uint32_t cc = 2 * ks + b_cc_add;
                uint32_t addr = bbase + row * 128 + ((cc << 4) ^ ((row & 7) << 4));
                ldsm4(bf[2 * L][0], bf[2 * L][1], bf[2 * L + 1][0], bf[2 * L + 1][1], addr);
            }
            #pragma unroll
            for (int ia = 0; ia < 4; ia++)
                #pragma unroll
                for (int j = 0; j < 8; j++)
                    mma16816(acc[ia][j], af[ia], bf[j]);
        }
    }

    // direct register epilogue: tile (float2 rows) + optional whole-tile mirror
    float* Cb = C + (size_t)b * NN * NN;
    const int g = lane >> 2, q = lane & 3;
    #pragma unroll
    for (int ia = 0; ia < 4; ia++) {
        int row = m0 + wm * 64 + ia * 16 + g;
        #pragma unroll
        for (int j = 0; j < 8; j++) {
            int col = n0 + wn * 64 + j * 8 + q * 2;
            *(float2*)&Cb[(size_t)row * NN + col]       = make_float2(acc[ia][j][0], acc[ia][j][1]);
            *(float2*)&Cb[(size_t)(row + 8) * NN + col] = make_float2(acc[ia][j][2], acc[ia][j][3]);
        }
    }
    if (do_mirror) {
        #pragma unroll
        for (int ia = 0; ia < 4; ia++) {
            int row = m0 + wm * 64 + ia * 16 + g;
            #pragma unroll
            for (int j = 0; j < 8; j++) {
                int col = n0 + wn * 64 + j * 8 + q * 2;
                Cb[(size_t)col * NN + row]           = acc[ia][j][0];
                Cb[(size_t)(col + 1) * NN + row]     = acc[ia][j][1];
                Cb[(size_t)col * NN + row + 8]       = acc[ia][j][2];
                Cb[(size_t)(col + 1) * NN + row + 8] = acc[ia][j][3];
            }
        }
    }
}

// ---------------- 5) radix-select top-64 (per-warp hist pass 1) + fused output ----------------
__global__ void __launch_bounds__(256) topk_out_kernel(float* __restrict__ out)
{
    const int n = blockIdx.x;
    const int b = blockIdx.y;
    const int t = threadIdx.x;
    const int wid = t >> 5;

    __shared__ int      hist8[8][256];
    __shared__ int      hist[256];
    __shared__ unsigned sh_prefix;
    __shared__ int      sh_krem;
    __shared__ float    red_f[8];
    __shared__ int      sel_idx[KTOP];
    __shared__ unsigned sel_key[KTOP];
    __shared__ float    sel_w[KTOP];
    __shared__ int      eq_idx[128];
    __shared__ int      cnt_gt, cnt_eq;
    __shared__ float    Zsh;

    const float* row = g_cos + ((size_t)b * NN + n) * NN;

    unsigned kreg[16];
    #pragma unroll
    for (int j = 0; j < 4; j++) {
        float4 v = *(const float4*)&row[1024 * j + 4 * t];
        const float vv[4] = {v.x, v.y, v.z, v.w};
        #pragma unroll
        for (int q = 0; q < 4; q++) {
            unsigned x = __float_as_uint(vv[q]);
            kreg[4 * j + q] = (x & 0x80000000u) ? ~x : (x | 0x80000000u);
        }
    }
    if (t == 0) { cnt_gt = 0; cnt_eq = 0; }
    #pragma unroll
    for (int w = 0; w < 8; w++) hist8[w][t] = 0;
    __syncthreads();

    // ---- pass d=3 with per-warp histograms ----
    #pragma unroll
    for (int j = 0; j < 16; j++) atomicAdd(&hist8[wid][kreg[j] >> 24], 1);
    __syncthreads();
    if (t < 32) {
        int bins[8], local = 0;
        #pragma unroll
        for (int i2 = 0; i2 < 8; i2++) {
            int bin = 255 - 8 * t - i2, s = 0;
            #pragma unroll
            for (int w = 0; w < 8; w++) s += hist8[w][bin];
            bins[i2] = s; local += s;
        }
        int excl = local;
        #pragma unroll
        for (int o = 1; o < 32; o <<= 1) {
            int v = __shfl_up_sync(0xffffffffu, excl, o);
            if (t >= o) excl += v;
        }
        excl -= local;
        if (excl < KTOP && KTOP <= excl + local) {
            int run = excl, digit = 0, gt_before = excl;
            #pragma unroll
            for (int i2 = 0; i2 < 8; i2++) {
                if (run + bins[i2] >= KTOP) { digit = 255 - 8 * t - i2; gt_before = run; break; }
                run += bins[i2];
            }
            sh_prefix = (unsigned)digit << 24;
            sh_krem = KTOP - gt_before;
        }
    }
    __syncthreads();

    // ---- passes d=2..0 (few participants, single hist) ----
    #pragma unroll
    for (int d = 2; d >= 0; d--) {
        hist[t] = 0;
        __syncthreads();
        const unsigned prefix = sh_prefix;
        const int krem = sh_krem;
        const int shift = d * 8;
        const unsigned mask = 0xFFFFFFFFu << (8 * (d + 1));
        #pragma unroll
        for (int j = 0; j < 16; j++) {
            unsigned u = kreg[j];
            if ((u & mask) == prefix) atomicAdd(&hist[(u >> shift) & 0xFF], 1);
        }
        __syncthreads();
        if (t < 32) {
            int bins[8], local = 0;
            #pragma unroll
            for (int i2 = 0; i2 < 8; i2++) { bins[i2] = hist[255 - 8 * t - i2]; local += bins[i2]; }
            int excl = local;
            #pragma unroll
            for (int o = 1; o < 32; o <<= 1) {
                int v = __shfl_up_sync(0xffffffffu, excl, o);
                if (t >= o) excl += v;
            }
            excl -= local;
            if (excl < krem && krem <= excl + local) {
                int run = excl, digit = 0, gt_before = excl;
                #pragma unroll
                for (int i2 = 0; i2 < 8; i2++) {
                    if (run + bins[i2] >= krem) { digit = 255 - 8 * t - i2; gt_before = run; break; }
                    run += bins[i2];
                }
                sh_prefix = prefix | ((unsigned)digit << shift);
                sh_krem = krem - gt_before;
            }
        }
        __syncthreads();
    }
    const unsigned ustar = sh_prefix;
    const int r = sh_krem;

    #pragma unroll
    for (int j = 0; j < 16; j++) {
        unsigned u = kreg[j];
        int idx = ((j >> 2) << 10) + (t << 2) + (j & 3);
        if (u > ustar) {
            int p = atomicAdd(&cnt_gt, 1);
            sel_idx[p] = idx;
            sel_key[p] = u;
        } else if (u == ustar) {
            int p = atomicAdd(&cnt_eq, 1);
            if (p < 128) eq_idx[p] = idx;
        }
    }
    __syncthreads();

    const int ngt = cnt_gt;
    if (t == 0) {
        int ne = cnt_eq < 128 ? cnt_eq : 128;
        for (int a = 1; a < ne; a++) {
            int v = eq_idx[a]; int c2 = a - 1;
            while (c2 >= 0 && eq_idx[c2] > v) { eq_idx[c2 + 1] = eq_idx[c2]; c2--; }
            eq_idx[c2 + 1] = v;
        }
        for (int a = 0; a < r; a++) { sel_idx[ngt + a] = eq_idx[a]; sel_key[ngt + a] = ustar; }
    }
    __syncthreads();

    float e_val = 0.f;
    if (t < KTOP) {
        unsigned u = sel_key[t];
        float v = (u & 0x80000000u) ? __uint_as_float(u & 0x7FFFFFFFu) : __uint_as_float(~u);
        e_val = expf(v);
        sel_w[t] = e_val - 1.0f;
    }
    float s = e_val;
    #pragma unroll
    for (int o = 16; o; o >>= 1) s += __shfl_xor_sync(0xffffffffu, s, o);
    if ((t & 31) == 0) red_f[t >> 5] = s;
    __syncthreads();
    if (t == 0) {
        float z = (float)(NN - KTOP);
        #pragma unroll
        for (int w = 0; w < 8; w++) z += red_f[w];
        Zsh = z;
    }
    __syncthreads();

    const float* Vb = g_value + (size_t)b * NN * DD;
    float acc = g_sumv[b * DD + t];
    const float invZ = 1.0f / Zsh;
    #pragma unroll 8
    for (int k = 0; k < KTOP; k++)
        acc += sel_w[k] * Vb[(size_t)sel_idx[k] * DD + t];
    out[((size_t)b * NN + n) * DD + t] = acc * invZ;
}

// ---------------- launch ----------------
extern "C" void kernel_launch(void* const* d_in, const int* in_sizes, int n_in,
                              void* d_out, int out_size)
{
    const float* x    = (const float*)d_in[0];
    const float* W    = (const float*)d_in[1];
    const float* bias = (const float*)d_in[2];
    float*       out  = (float*)d_out;

    float* p_cos;
    cudaGetSymbolAddress((void**)&p_cos, g_cos);

    const int VAL_SMEM = 3 * 32768;    // 98304
    const int COS_SMEM = 3 * 49152;    // 147456
    cudaFuncSetAttribute(cosmma_kernel,   cudaFuncAttributeMaxDynamicSharedMemorySize, COS_SMEM);
    cudaFuncSetAttribute(valuemma_kernel, cudaFuncAttributeMaxDynamicSharedMemorySize, VAL_SMEM);

    normalize_pack_kernel<<<BB * NN, DD>>>(x, W);                                   // #1
    xsum_part_kernel<<<dim3(16, BB), DD>>>(x);                                      // #2
    sumv_mv_kernel<<<BB, DD>>>(W, bias);                                            // #3
    cosmma_kernel<<<dim3(16 * 17, 1, BB), 256, COS_SMEM>>>(p_cos);                  // #4 (profiler)
    valuemma_kernel<<<dim3(DD / 128, (BB * NN) / 128), 256, VAL_SMEM>>>(bias);      // #5
    topk_out_kernel<<<dim3(NN, BB), 256>>>(out);                                    // #6
}

// round 10
// speedup vs baseline: 1.1797x; 1.1797x over previous
#include <cuda_runtime.h>
#include <cuda_bf16.h>
#include <cstdint>
#include <math.h>

#define BB 4
#define NN 4096
#define DD 256
#define KTOP 64
#define EPSN 1e-12f

#define PACKW 512             // [hi(256) | lo(256)] per row
#define NCHUNK_V 12           // value: full 3-term split
#define NCHUNK_C 8            // cos: H·(H+L)^T

// ---------------- scratch ----------------
__device__ __nv_bfloat16  g_value[(size_t)BB * NN * DD];          // bf16 value (gather-only consumer)
__device__ float          g_cos  [(size_t)BB * NN * NN];
__device__ __nv_bfloat16  g_pack [(size_t)BB * NN * PACKW];
__device__ __nv_bfloat16  g_Wpack[(size_t)DD * PACKW];
__device__ float          g_norm [(size_t)BB * NN];
__device__ float          g_xsum_part[BB * 16 * DD];
__device__ float          g_sumv[BB * DD];

__device__ __constant__ int CAMAP_V[NCHUNK_V] = {0,1,2,3, 0,1,2,3, 4,5,6,7};
__device__ __constant__ int CBMAP_V[NCHUNK_V] = {0,1,2,3, 4,5,6,7, 0,1,2,3};

__device__ __forceinline__ uint32_t smem_to_u32(const void* p) {
    uint32_t a;
    asm("{ .reg .u64 t; cvta.to.shared.u64 t, %1; cvt.u32.u64 %0, t; }" : "=r"(a) : "l"(p));
    return a;
}
__device__ __forceinline__ void ldsm4(uint32_t& r0, uint32_t& r1, uint32_t& r2, uint32_t& r3, uint32_t addr) {
    asm volatile("ldmatrix.sync.aligned.m8n8.x4.shared.b16 {%0,%1,%2,%3}, [%4];"
        : "=r"(r0), "=r"(r1), "=r"(r2), "=r"(r3) : "r"(addr));
}
__device__ __forceinline__ void mma16816(float* d, const uint32_t* a, const uint32_t* b) {
    asm volatile("mma.sync.aligned.m16n8k16.row.col.f32.bf16.bf16.f32 "
        "{%0,%1,%2,%3}, {%4,%5,%6,%7}, {%8,%9}, {%0,%1,%2,%3};"
        : "+f"(d[0]), "+f"(d[1]), "+f"(d[2]), "+f"(d[3])
        : "r"(a[0]), "r"(a[1]), "r"(a[2]), "r"(a[3]), "r"(b[0]), "r"(b[1]));
}
__device__ __forceinline__ void cp_async16(uint32_t saddr, const void* gptr) {
    asm volatile("cp.async.cg.shared.global [%0], [%1], 16;" :: "r"(saddr), "l"(gptr) : "memory");
}
#define CP_COMMIT() asm volatile("cp.async.commit_group;" ::: "memory")
#define CP_WAIT(N)  asm volatile("cp.async.wait_group %0;" :: "n"(N) : "memory")

// ---------------- 1) normalize + hi/lo pack + norm save (+ W pack piggyback) ----------------
__global__ void __launch_bounds__(DD) normalize_pack_kernel(const float* __restrict__ x,
                                                            const float* __restrict__ W)
{
    int row = blockIdx.x;
    int d   = threadIdx.x;
    float v = x[(size_t)row * DD + d];
    float s = v * v;
    __shared__ float red[8];
    #pragma unroll
    for (int o = 16; o; o >>= 1) s += __shfl_xor_sync(0xffffffffu, s, o);
    if ((d & 31) == 0) red[d >> 5] = s;
    __syncthreads();
    if (d < 32) {
        float t = (d < 8) ? red[d] : 0.f;
        #pragma unroll
        for (int o = 4; o; o >>= 1) t += __shfl_xor_sync(0xffffffffu, t, o);
        if (d == 0) red[0] = t;
    }
    __syncthreads();
    float norm = sqrtf(red[0]);
    float nv = v / fmaxf(norm, EPSN);

    __nv_bfloat16 hi = __float2bfloat16(nv);
    __nv_bfloat16 lo = __float2bfloat16(nv - __bfloat162float(hi));

    size_t base = (size_t)row * PACKW;
    g_pack[base + d]       = hi;
    g_pack[base + 256 + d] = lo;
    if (d == 0) g_norm[row] = norm;

    if (row < DD) {
        float w = W[(size_t)row * DD + d];
        __nv_bfloat16 whi = __float2bfloat16(w);
        __nv_bfloat16 wlo = __float2bfloat16(w - __bfloat162float(whi));
        g_Wpack[(size_t)row * PACKW + d]       = whi;
        g_Wpack[(size_t)row * PACKW + 256 + d] = wlo;
    }
}

// ---------------- 1b) per-batch partial column sums of x ----------------
__global__ void __launch_bounds__(DD) xsum_part_kernel(const float* __restrict__ x)
{
    int b = blockIdx.y, c = blockIdx.x, e = threadIdx.x;
    const float* base = x + (size_t)b * NN * DD + (size_t)c * 256 * DD + e;
    float s = 0.f;
    #pragma unroll 8
    for (int n = 0; n < 256; n++) s += base[(size_t)n * DD];
    g_xsum_part[(b * 16 + c) * DD + e] = s;
}

// ---------------- 1c) sumv = (colsum x) @ W^T + N*b  (exact algebra) ----------------
__global__ void __launch_bounds__(DD) sumv_mv_kernel(const float* __restrict__ W,
                                                     const float* __restrict__ bias)
{
    int b = blockIdx.x, t = threadIdx.x;
    __shared__ float xs[DD];
    float s = 0.f;
    #pragma unroll
    for (int c = 0; c < 16; c++) s += g_xsum_part[(b * 16 + c) * DD + t];
    xs[t] = s;
    __syncthreads();
    float acc = 0.f;
    const float4* Wr = (const float4*)&W[(size_t)t * DD];
    #pragma unroll 8
    for (int d4 = 0; d4 < 64; d4++) {
        float4 w = Wr[d4];
        acc += xs[d4 * 4 + 0] * w.x + xs[d4 * 4 + 1] * w.y
             + xs[d4 * 4 + 2] * w.z + xs[d4 * 4 + 3] * w.w;
    }
    g_sumv[b * DD + t] = acc + (float)NN * bias[t];
}

// ---------------- 2) value = norm * (nx @ W^T) + b  -> bf16  (mma, 3-stage, 128x128) ----------------
__global__ void __launch_bounds__(256, 2) valuemma_kernel(const float* __restrict__ bias)
{
    extern __shared__ char smem[];
    const uint32_t sb = smem_to_u32(smem);

    const int tid  = threadIdx.x;
    const int wid  = tid >> 5;
    const int lane = tid & 31;
    const int wm   = wid & 3;
    const int wn   = wid >> 2;
    const int m0   = blockIdx.y * 128;
    const int n0   = blockIdx.x * 128;

    const __nv_bfloat16* Agl = g_pack  + (size_t)m0 * PACKW;
    const __nv_bfloat16* Bgl = g_Wpack + (size_t)n0 * PACKW;

    const int lr = tid >> 3;
    const int lj = tid & 7;

    auto load_chunk_async = [&](int c, int s) {
        const char* ga = (const char*)Agl + (size_t)CAMAP_V[c] * 128;
        const char* gb = (const char*)Bgl + (size_t)CBMAP_V[c] * 128;
        uint32_t sa = sb + s * 32768;
        uint32_t sbm = sa + 16384;
        #pragma unroll
        for (int k = 0; k < 4; k++) {
            int r = lr + 32 * k;
            uint32_t off = r * 128 + ((lj ^ (r & 7)) << 4);
            cp_async16(sa + off,  ga + (size_t)r * (PACKW * 2) + lj * 16);
            cp_async16(sbm + off, gb + (size_t)r * (PACKW * 2) + lj * 16);
        }
    };

    float acc[2][8][4];
    #pragma unroll
    for (int ia = 0; ia < 2; ia++)
        #pragma unroll
        for (int j = 0; j < 8; j++)
            #pragma unroll
            for (int q = 0; q < 4; q++) acc[ia][j][q] = 0.f;

    const int arow_lo = (lane & 7) + ((lane >> 3) & 1) * 8;
    const int a_cc_add = (lane >> 4);
    const int brow_lo = (lane & 7) + ((lane >> 4) ? 8 : 0);
    const int b_cc_add = ((lane >> 3) & 1);

    load_chunk_async(0, 0); CP_COMMIT();
    load_chunk_async(1, 1); CP_COMMIT();

    for (int c = 0; c < NCHUNK_V; c++) {
        if (c + 1 < NCHUNK_V) { CP_WAIT(1); } else { CP_WAIT(0); }
        __syncthreads();
        if (c + 2 < NCHUNK_V) { load_chunk_async(c + 2, (c + 2) % 3); CP_COMMIT(); }

        const uint32_t abase = sb + (c % 3) * 32768;
        const uint32_t bbase = abase + 16384;

        #pragma unroll
        for (int ks = 0; ks < 4; ks++) {
            uint32_t af[2][4], bf[8][2];
            #pragma unroll
            for (int ia = 0; ia < 2; ia++) {
                int row = wm * 32 + ia * 16 + arow_lo;
                uint32_t cc = 2 * ks + a_cc_add;
                uint32_t addr = abase + row * 128 + ((cc << 4) ^ ((row & 7) << 4));
                ldsm4(af[ia][0], af[ia][1], af[ia][2], af[ia][3], addr);
            }
            #pragma unroll
            for (int L = 0; L < 4; L++) {
                int row = wn * 64 + L * 16 + brow_lo;
                uint32_t cc = 2 * ks + b_cc_add;
                uint32_t addr = bbase + row * 128 + ((cc << 4) ^ ((row & 7) << 4));
                ldsm4(bf[2 * L][0], bf[2 * L][1], bf[2 * L + 1][0], bf[2 * L + 1][1], addr);
            }
            #pragma unroll
            for (int ia = 0; ia < 2; ia++)
                #pragma unroll
                for (int j = 0; j < 8; j++)
                    mma16816(acc[ia][j], af[ia], bf[j]);
        }
    }

    // epilogue: scale by norm, add bias, store bf16x2
    const int g = lane >> 2, q = lane & 3;
    #pragma unroll
    for (int ia = 0; ia < 2; ia++) {
        int row = m0 + wm * 32 + ia * 16 + g;
        float nr0 = __ldg(&g_norm[row]);
        float nr8 = __ldg(&g_norm[row + 8]);
        #pragma unroll
        for (int j = 0; j < 8; j++) {
            int col = n0 + wn * 64 + j * 8 + q * 2;
            float b0 = __ldg(&bias[col]), b1 = __ldg(&bias[col + 1]);
            __nv_bfloat162 v01 = __floats2bfloat162_rn(acc[ia][j][0] * nr0 + b0, acc[ia][j][1] * nr0 + b1);
            __nv_bfloat162 v23 = __floats2bfloat162_rn(acc[ia][j][2] * nr8 + b0, acc[ia][j][3] * nr8 + b1);
            *(__nv_bfloat162*)&g_value[(size_t)row * DD + col]       = v01;
            *(__nv_bfloat162*)&g_value[(size_t)(row + 8) * DD + col] = v23;
        }
    }
}

// ---------------- 4) cos = H @ (H+L)^T  (R8 config: 128x128, 3-stage, direct epilogue) ----------------
__global__ void __launch_bounds__(256, 2) cosmma_kernel(float* __restrict__ C)
{
    extern __shared__ char smem[];
    const uint32_t sb = smem_to_u32(smem);

    const int tid  = threadIdx.x;
    const int wid  = tid >> 5;
    const int lane = tid & 31;
    const int wm   = wid & 3;
    const int wn   = wid >> 2;
    const int b    = blockIdx.z;

    int i  = blockIdx.x;
    int by = (int)((sqrtf(8.f * (float)i + 1.f) - 1.f) * 0.5f);
    while ((by + 1) * (by + 2) / 2 <= i) by++;
    while (by * (by + 1) / 2 > i) by--;
    int bx = i - by * (by + 1) / 2;
    const int m0 = by * 128;
    const int n0 = bx * 128;

    const __nv_bfloat16* Agl = g_pack + ((size_t)b * NN + m0) * PACKW;
    const __nv_bfloat16* Bgl = g_pack + ((size_t)b * NN + n0) * PACKW;

    const int lr = tid >> 3;
    const int lj = tid & 7;

    auto load_chunk_async = [&](int c, int s) {
        const char* ga = (const char*)Agl + (size_t)(c & 3) * 128;   // hi only
        const char* gb = (const char*)Bgl + (size_t)c * 128;         // hi then lo
        uint32_t sa = sb + s * 32768;
        uint32_t sbm = sa + 16384;
        #pragma unroll
        for (int k = 0; k < 4; k++) {
            int r = lr + 32 * k;
            uint32_t off = r * 128 + ((lj ^ (r & 7)) << 4);
            cp_async16(sa + off,  ga + (size_t)r * (PACKW * 2) + lj * 16);
            cp_async16(sbm + off, gb + (size_t)r * (PACKW * 2) + lj * 16);
        }
    };

    float acc[2][8][4];
    #pragma unroll
    for (int ia = 0; ia < 2; ia++)
        #pragma unroll
        for (int j = 0; j < 8; j++)
            #pragma unroll
            for (int q = 0; q < 4; q++) acc[ia][j][q] = 0.f;

    const int arow_lo = (lane & 7) + ((lane >> 3) & 1) * 8;
    const int a_cc_add = (lane >> 4);
    const int brow_lo = (lane & 7) + ((lane >> 4) ? 8 : 0);
    const int b_cc_add = ((lane >> 3) & 1);

    load_chunk_async(0, 0); CP_COMMIT();
    load_chunk_async(1, 1); CP_COMMIT();

    for (int c = 0; c < NCHUNK_C; c++) {
        if (c + 1 < NCHUNK_C) { CP_WAIT(1); } else { CP_WAIT(0); }
        __syncthreads();
        if (c + 2 < NCHUNK_C) { load_chunk_async(c + 2, (c + 2) % 3); CP_COMMIT(); }

        const uint32_t abase = sb + (c % 3) * 32768;
        const uint32_t bbase = abase + 16384;

        #pragma unroll
        for (int ks = 0; ks < 4; ks++) {
            uint32_t af[2][4], bf[8][2];
            #pragma unroll
            for (int ia = 0; ia < 2; ia++) {
                int row = wm * 32 + ia * 16 + arow_lo;
                uint32_t cc = 2 * ks + a_cc_add;
                uint32_t addr = abase + row * 128 + ((cc << 4) ^ ((row & 7) << 4));
                ldsm4(af[ia][0], af[ia][1], af[ia][2], af[ia][3], addr);
            }
            #pragma unroll
            for (int L = 0; L < 4; L++) {
                int row = wn * 64 + L * 16 + brow_lo;
                uint32_t cc = 2 * ks + b_cc_add;
                uint32_t addr = bbase + row * 128 + ((cc << 4) ^ ((row & 7) << 4));
                ldsm4(bf[2 * L][0], bf[2 * L][1], bf[2 * L + 1][0], bf[2 * L + 1][1], addr);
            }
            #pragma unroll
            for (int ia = 0; ia < 2; ia++)
                #pragma unroll
                for (int j = 0; j < 8; j++)
                    mma16816(acc[ia][j], af[ia], bf[j]);
        }
    }

    float* Cb = C + (size_t)b * NN * NN;
    const int g = lane >> 2, q = lane & 3;
    #pragma unroll
    for (int ia = 0; ia < 2; ia++) {
        int row = m0 + wm * 32 + ia * 16 + g;
        #pragma unroll
        for (int j = 0; j < 8; j++) {
            int col = n0 + wn * 64 + j * 8 + q * 2;
            *(float2*)&Cb[(size_t)row * NN + col]       = make_float2(acc[ia][j][0], acc[ia][j][1]);
            *(float2*)&Cb[(size_t)(row + 8) * NN + col] = make_float2(acc[ia][j][2], acc[ia][j][3]);
        }
    }
    if (bx != by) {
        #pragma unroll
        for (int ia = 0; ia < 2; ia++) {
            int row = m0 + wm * 32 + ia * 16 + g;
            #pragma unroll
            for (int j = 0; j < 8; j++) {
                int col = n0 + wn * 64 + j * 8 + q * 2;
                Cb[(size_t)col * NN + row]           = acc[ia][j][0];
                Cb[(size_t)(col + 1) * NN + row]     = acc[ia][j][1];
                Cb[(size_t)col * NN + row + 8]       = acc[ia][j][2];
                Cb[(size_t)(col + 1) * NN + row + 8] = acc[ia][j][3];
            }
        }
    }
}

// ---------------- 5) radix-select top-64 (R8 version) + fused output (bf16 gather) ----------------
__global__ void __launch_bounds__(256) topk_out_kernel(float* __restrict__ out)
{
    const int n = blockIdx.x;
    const int b = blockIdx.y;
    const int t = threadIdx.x;

    __shared__ int      hist[256];
    __shared__ unsigned sh_prefix;
    __shared__ int      sh_krem;
    __shared__ float    red_f[8];
    __shared__ int      sel_idx[KTOP];
    __shared__ unsigned sel_key[KTOP];
    __shared__ float    sel_w[KTOP];
    __shared__ int      eq_idx[128];
    __shared__ int      cnt_gt, cnt_eq;
    __shared__ float    Zsh;

    const float* row = g_cos + ((size_t)b * NN + n) * NN;

    unsigned kreg[16];
    #pragma unroll
    for (int j = 0; j < 4; j++) {
        float4 v = *(const float4*)&row[1024 * j + 4 * t];
        const float vv[4] = {v.x, v.y, v.z, v.w};
        #pragma unroll
        for (int q = 0; q < 4; q++) {
            unsigned x = __float_as_uint(vv[q]);
            kreg[4 * j + q] = (x & 0x80000000u) ? ~x : (x | 0x80000000u);
        }
    }
    if (t == 0) { sh_prefix = 0u; sh_krem = KTOP; cnt_gt = 0; cnt_eq = 0; }
    __syncthreads();

    #pragma unroll
    for (int d = 3; d >= 0; d--) {
        hist[t] = 0;
        __syncthreads();
        const unsigned prefix = sh_prefix;
        const int krem = sh_krem;
        const int shift = d * 8;
        const unsigned mask = (d == 3) ? 0u : (0xFFFFFFFFu << (8 * (d + 1)));
        #pragma unroll
        for (int j = 0; j < 16; j++) {
            unsigned u = kreg[j];
            if ((u & mask) == prefix) atomicAdd(&hist[(u >> shift) & 0xFF], 1);
        }
        __syncthreads();
        if (t < 32) {
            int bins[8], local = 0;
            #pragma unroll
            for (int i2 = 0; i2 < 8; i2++) { bins[i2] = hist[255 - 8 * t - i2]; local += bins[i2]; }
            int excl = local;
            #pragma unroll
            for (int o = 1; o < 32; o <<= 1) {
                int v = __shfl_up_sync(0xffffffffu, excl, o);
                if (t >= o) excl += v;
            }
            excl -= local;
            if (excl < krem && krem <= excl + local) {
                int run = excl, digit = 0, gt_before = excl;
                #pragma unroll
                for (int i2 = 0; i2 < 8; i2++) {
                    if (run + bins[i2] >= krem) { digit = 255 - 8 * t - i2; gt_before = run; break; }
                    run += bins[i2];
                }
                sh_prefix = prefix | ((unsigned)digit << shift);
                sh_krem = krem - gt_before;
            }
        }
        __syncthreads();
    }
    const unsigned ustar = sh_prefix;
    const int r = sh_krem;

    #pragma unroll
    for (int j = 0; j < 16; j++) {
        unsigned u = kreg[j];
        int idx = ((j >> 2) << 10) + (t << 2) + (j & 3);
        if (u > ustar) {
            int p = atomicAdd(&cnt_gt, 1);
            sel_idx[p] = idx;
            sel_key[p] = u;
        } else if (u == ustar) {
            int p = atomicAdd(&cnt_eq, 1);
            if (p < 128) eq_idx[p] = idx;
        }
    }
    __syncthreads();

    const int ngt = cnt_gt;
    if (t == 0) {
        int ne = cnt_eq < 128 ? cnt_eq : 128;
        for (int a = 1; a < ne; a++) {
            int v = eq_idx[a]; int c2 = a - 1;
            while (c2 >= 0 && eq_idx[c2] > v) { eq_idx[c2 + 1] = eq_idx[c2]; c2--; }
            eq_idx[c2 + 1] = v;
        }
        for (int a = 0; a < r; a++) { sel_idx[ngt + a] = eq_idx[a]; sel_key[ngt + a] = ustar; }
    }
    __syncthreads();

    float e_val = 0.f;
    if (t < KTOP) {
        unsigned u = sel_key[t];
        float v = (u & 0x80000000u) ? __uint_as_float(u & 0x7FFFFFFFu) : __uint_as_float(~u);
        e_val = expf(v);
        sel_w[t] = e_val - 1.0f;
    }
    float s = e_val;
    #pragma unroll
    for (int o = 16; o; o >>= 1) s += __shfl_xor_sync(0xffffffffu, s, o);
    if ((t & 31) == 0) red_f[t >> 5] = s;
    __syncthreads();
    if (t == 0) {
        float z = (float)(NN - KTOP);
        #pragma unroll
        for (int w = 0; w < 8; w++) z += red_f[w];
        Zsh = z;
    }
    __syncthreads();

    const __nv_bfloat16* Vb = g_value + (size_t)b * NN * DD;
    float acc = g_sumv[b * DD + t];
    const float invZ = 1.0f / Zsh;
    #pragma unroll 8
    for (int k = 0; k < KTOP; k++)
        acc += sel_w[k] * __bfloat162float(Vb[(size_t)sel_idx[k] * DD + t]);
    out[((size_t)b * NN + n) * DD + t] = acc * invZ;
}

// ---------------- launch ----------------
extern "C" void kernel_launch(void* const* d_in, const int* in_sizes, int n_in,
                              void* d_out, int out_size)
{
    const float* x    = (const float*)d_in[0];
    const float* W    = (const float*)d_in[1];
    const float* bias = (const float*)d_in[2];
    float*       out  = (float*)d_out;

    float* p_cos;
    cudaGetSymbolAddress((void**)&p_cos, g_cos);

    const int MMA_SMEM = 3 * 32768;
    cudaFuncSetAttribute(cosmma_kernel,   cudaFuncAttributeMaxDynamicSharedMemorySize, MMA_SMEM);
    cudaFuncSetAttribute(valuemma_kernel, cudaFuncAttributeMaxDynamicSharedMemorySize, MMA_SMEM);

    normalize_pack_kernel<<<BB * NN, DD>>>(x, W);                                   // #1
    xsum_part_kernel<<<dim3(16, BB), DD>>>(x);                                      // #2
    valuemma_kernel<<<dim3(DD / 128, (BB * NN) / 128), 256, MMA_SMEM>>>(bias);      // #3 (pack L2-warm)
    cosmma_kernel<<<dim3((NN / 128) * (NN / 128 + 1) / 2, 1, BB), 256, MMA_SMEM>>>(p_cos);  // #4 (profiler)
    sumv_mv_kernel<<<BB, DD>>>(W, bias);                                            // #5
    topk_out_kernel<<<dim3(NN, BB), 256>>>(out);                                    // #6
}